// round 3
// baseline (speedup 1.0000x reference)
#include <cuda_runtime.h>

// CTC greedy search, fused single persistent kernel.
//   logits: (T=2048, N=32, V=1024) float32, batch_first = False
//   in_lens: (N,) int (int32 or int64 — detected at runtime)
// Output (float32): [ max_total (N) | paths (T*N, t*N+n) | out_lens (N) ]

#define T_DIM 2048
#define N_DIM 32
#define V_DIM 1024
#define BLANK 1023        // (-1 + V) % V
#define GRID_B 444        // 148 SMs * 3 blocks — guaranteed resident (1 wave)
#define TPB 256
#define NWARPS (GRID_B * (TPB / 32))

// Scratch + barrier state (__device__ globals; zero-initialized at load).
__device__ int   g_amax[(size_t)T_DIM * N_DIM];   // n-major
__device__ float g_maxv[(size_t)T_DIM * N_DIM];
__device__ int   g_arrive;
__device__ int   g_ack;

__global__ void __launch_bounds__(TPB, 3) ctc_fused_kernel(
    const float* __restrict__ logits,
    const void* __restrict__ in_lens_raw,
    float* __restrict__ out)
{
    const int tid  = threadIdx.x;
    const int lane = tid & 31;
    const int wid  = tid >> 5;

    float* out_paths = out + N_DIM;

    // =====================================================================
    // Phase 1: row max/argmax/logsumexp. One warp per (t,n) row, persistent.
    // =====================================================================
    for (int task = blockIdx.x * (TPB / 32) + wid; task < T_DIM * N_DIM;
         task += NWARPS) {
        const float4* row =
            reinterpret_cast<const float4*>(logits) + (size_t)task * (V_DIM / 4);

        float4 v[8];
#pragma unroll
        for (int k = 0; k < 8; k++) v[k] = row[lane + 32 * k];

        float m = -1e30f; int mi = 0;
#pragma unroll
        for (int k = 0; k < 8; k++) {
            const int base = (lane + 32 * k) * 4;
            float x;
            x = v[k].x; if (x > m) { m = x; mi = base;     }
            x = v[k].y; if (x > m) { m = x; mi = base + 1; }
            x = v[k].z; if (x > m) { m = x; mi = base + 2; }
            x = v[k].w; if (x > m) { m = x; mi = base + 3; }
        }
#pragma unroll
        for (int off = 16; off; off >>= 1) {
            float om = __shfl_down_sync(0xffffffffu, m, off);
            int  omi = __shfl_down_sync(0xffffffffu, mi, off);
            if (om > m || (om == m && omi < mi)) { m = om; mi = omi; }
        }
        m  = __shfl_sync(0xffffffffu, m, 0);
        mi = __shfl_sync(0xffffffffu, mi, 0);

        float s = 0.f;
#pragma unroll
        for (int k = 0; k < 8; k++) {
            s += __expf(v[k].x - m) + __expf(v[k].y - m)
               + __expf(v[k].z - m) + __expf(v[k].w - m);
        }
#pragma unroll
        for (int off = 16; off; off >>= 1)
            s += __shfl_down_sync(0xffffffffu, s, off);

        if (lane == 0) {
            const int t = task / N_DIM;
            const int n = task - t * N_DIM;
            g_amax[n * T_DIM + t] = mi;
            g_maxv[n * T_DIM + t] = -logf(s);
            out_paths[task] = (float)mi;   // masked_scatter default region
        }
    }

    // =====================================================================
    // Grid barrier (all GRID_B blocks resident by construction).
    // =====================================================================
    __threadfence();
    __syncthreads();
    if (tid == 0) {
        atomicAdd(&g_arrive, 1);
        while (atomicAdd(&g_arrive, 0) < GRID_B) __nanosleep(64);
    }
    __syncthreads();

    // =====================================================================
    // Phase 2: blocks 0..31 scan one batch row each (8 t's per thread).
    // =====================================================================
    __shared__ int   swc[8];
    __shared__ float sws[8];

    if (blockIdx.x < N_DIM) {
        const int n = blockIdx.x;

        // dtype-robust in_lens: values in [1,T]; int64 LE => high words are 0.
        const int* w32 = (const int*)in_lens_raw;
        const bool is64 = (w32[1] == 0);
        const int L = is64 ? (int)((const long long*)in_lens_raw)[n] : w32[n];

        const int*   a  = g_amax + n * T_DIM;
        const float* mv = g_maxv + n * T_DIM;

        const int t0 = tid * 8;
        const int4 A0 = reinterpret_cast<const int4*>(a)[2 * tid];
        const int4 A1 = reinterpret_cast<const int4*>(a)[2 * tid + 1];
        const float4 M0 = reinterpret_cast<const float4*>(mv)[2 * tid];
        const float4 M1 = reinterpret_cast<const float4*>(mv)[2 * tid + 1];

        int av[8] = {A0.x, A0.y, A0.z, A0.w, A1.x, A1.y, A1.z, A1.w};

        int prev = __shfl_up_sync(0xffffffffu, A1.w, 1);
        if (lane == 0) prev = (tid == 0) ? -123 : a[t0 - 1];

        bool k[8]; int cnt = 0; int p = prev;
#pragma unroll
        for (int i = 0; i < 8; i++) {
            k[i] = (av[i] != BLANK) && (av[i] != p) && (t0 + i < L);
            p = av[i];
            cnt += (int)k[i];
        }

        float loc = 0.f;
        loc += (t0 + 0 < L) ? M0.x : 0.f;
        loc += (t0 + 1 < L) ? M0.y : 0.f;
        loc += (t0 + 2 < L) ? M0.z : 0.f;
        loc += (t0 + 3 < L) ? M0.w : 0.f;
        loc += (t0 + 4 < L) ? M1.x : 0.f;
        loc += (t0 + 5 < L) ? M1.y : 0.f;
        loc += (t0 + 6 < L) ? M1.z : 0.f;
        loc += (t0 + 7 < L) ? M1.w : 0.f;

        int inc = cnt;
#pragma unroll
        for (int off = 1; off < 32; off <<= 1) {
            int v = __shfl_up_sync(0xffffffffu, inc, off);
            if (lane >= off) inc += v;
            loc += __shfl_down_sync(0xffffffffu, loc, off);
        }
        if (lane == 31) swc[wid] = inc;
        if (lane == 0)  sws[wid] = loc;
        __syncthreads();

        if (wid == 0) {
            int v = (lane < 8) ? swc[lane] : 0;
            int inc2 = v;
#pragma unroll
            for (int off = 1; off < 32; off <<= 1) {
                int u = __shfl_up_sync(0xffffffffu, inc2, off);
                if (lane >= off) inc2 += u;
            }
            if (lane < 8) swc[lane] = inc2 - v;          // exclusive offsets
            if (lane == 7)
                out[N_DIM + (size_t)T_DIM * N_DIM + n] = (float)inc2;  // out_lens

            float fs = (lane < 8) ? sws[lane] : 0.f;
#pragma unroll
            for (int off = 16; off; off >>= 1)
                fs += __shfl_down_sync(0xffffffffu, fs, off);
            if (lane == 0) out[n] = fs;                  // max_total
        }
        __syncthreads();

        int pos = swc[wid] + (inc - cnt);
        float* paths = out + N_DIM;
#pragma unroll
        for (int i = 0; i < 8; i++) {
            if (k[i]) { paths[pos * N_DIM + n] = (float)av[i]; pos++; }
        }
    }

    // =====================================================================
    // Ack + counter reset (last acker) so graph replays see zeroed state.
    // =====================================================================
    __syncthreads();
    if (tid == 0) {
        int o = atomicAdd(&g_ack, 1);
        if (o == GRID_B - 1) {
            atomicExch(&g_arrive, 0);
            atomicExch(&g_ack, 0);
            __threadfence();
        }
    }
}

// ---------------------------------------------------------------------------
extern "C" void kernel_launch(void* const* d_in, const int* in_sizes, int n_in,
                              void* d_out, int out_size)
{
    const float* logits = (const float*)d_in[0];
    const void*  lens   = d_in[1];
    float* out = (float*)d_out;

    (void)in_sizes; (void)n_in; (void)out_size;

    ctc_fused_kernel<<<GRID_B, TPB>>>(logits, lens, out);
}

// round 4
// speedup vs baseline: 1.0709x; 1.0709x over previous
#include <cuda_runtime.h>

// CTC greedy search, 2 kernels + PDL overlap.
//   logits: (T=2048, N=32, V=1024) float32, batch_first = False
//   in_lens: (N,) int (int32 or int64 — detected at runtime)
// Output (float32): [ max_total (N) | paths (T*N, t*N+n) | out_lens (N) ]

#define T_DIM 2048
#define N_DIM 32
#define V_DIM 1024
#define BLANK 1023   // (-1 + V) % V

// Scratch (allocation-free rule: __device__ globals). n-major for kernel2 coalescing.
__device__ int   g_amax[(size_t)T_DIM * N_DIM];
__device__ float g_maxv[(size_t)T_DIM * N_DIM];

// ---------------------------------------------------------------------------
// Kernel 1: one warp per (t, n) row of V=1024 logits. Proven ~6.5 TB/s.
// ---------------------------------------------------------------------------
__global__ void __launch_bounds__(256) ctc_rowmax_kernel(
    const float* __restrict__ logits, float* __restrict__ out_paths)
{
    const int warp_id = (blockIdx.x * 256 + threadIdx.x) >> 5;  // = t*N + n
    const int lane = threadIdx.x & 31;

    const float4* row =
        reinterpret_cast<const float4*>(logits) + (size_t)warp_id * (V_DIM / 4);

    float4 v[8];
#pragma unroll
    for (int k = 0; k < 8; k++) v[k] = row[lane + 32 * k];

    // per-lane max + first-occurrence argmax
    float m = -1e30f; int mi = 0;
#pragma unroll
    for (int k = 0; k < 8; k++) {
        const int base = (lane + 32 * k) * 4;
        float x;
        x = v[k].x; if (x > m) { m = x; mi = base;     }
        x = v[k].y; if (x > m) { m = x; mi = base + 1; }
        x = v[k].z; if (x > m) { m = x; mi = base + 2; }
        x = v[k].w; if (x > m) { m = x; mi = base + 3; }
    }
#pragma unroll
    for (int off = 16; off; off >>= 1) {
        float om = __shfl_down_sync(0xffffffffu, m, off);
        int  omi = __shfl_down_sync(0xffffffffu, mi, off);
        if (om > m || (om == m && omi < mi)) { m = om; mi = omi; }
    }
    m  = __shfl_sync(0xffffffffu, m, 0);
    mi = __shfl_sync(0xffffffffu, mi, 0);

    float s = 0.f;
#pragma unroll
    for (int k = 0; k < 8; k++) {
        s += __expf(v[k].x - m) + __expf(v[k].y - m)
           + __expf(v[k].z - m) + __expf(v[k].w - m);
    }
#pragma unroll
    for (int off = 16; off; off >>= 1) s += __shfl_down_sync(0xffffffffu, s, off);

    if (lane == 0) {
        const int t = warp_id / N_DIM;
        const int n = warp_id - t * N_DIM;
        g_amax[n * T_DIM + t] = mi;
        g_maxv[n * T_DIM + t] = -logf(s);      // max over V of log_softmax
        out_paths[warp_id] = (float)mi;        // masked_scatter default region
    }
}

// ---------------------------------------------------------------------------
// Kernel 2: one 256-thread block per batch row, 8 t's per thread, single pass.
// Launched with PDL: blocks spin up during K1; data reads gated by
// cudaGridDependencySynchronize().
// ---------------------------------------------------------------------------
__global__ void __launch_bounds__(256) ctc_scan_kernel(
    const void* __restrict__ in_lens_raw, float* __restrict__ out)
{
    const int n    = blockIdx.x;
    const int tid  = threadIdx.x;     // 0..255
    const int lane = tid & 31;
    const int wid  = tid >> 5;        // 0..7

    __shared__ int   swc[8];
    __shared__ float sws[8];

    // Wait for K1's results to be visible (PDL gate).
    cudaGridDependencySynchronize();

    // dtype-robust in_lens: values in [1,T]; int64 LE => high words are 0.
    const int* w32 = (const int*)in_lens_raw;
    const bool is64 = (w32[1] == 0);
    const int L = is64 ? (int)((const long long*)in_lens_raw)[n] : w32[n];

    const int*   a  = g_amax + n * T_DIM;
    const float* mv = g_maxv + n * T_DIM;

    const int t0 = tid * 8;
    const int4 A0 = reinterpret_cast<const int4*>(a)[2 * tid];
    const int4 A1 = reinterpret_cast<const int4*>(a)[2 * tid + 1];
    const float4 M0 = reinterpret_cast<const float4*>(mv)[2 * tid];
    const float4 M1 = reinterpret_cast<const float4*>(mv)[2 * tid + 1];

    int av[8] = {A0.x, A0.y, A0.z, A0.w, A1.x, A1.y, A1.z, A1.w};

    int prev = __shfl_up_sync(0xffffffffu, A1.w, 1);
    if (lane == 0) prev = (tid == 0) ? -123 : a[t0 - 1];

    bool k[8]; int cnt = 0; int p = prev;
#pragma unroll
    for (int i = 0; i < 8; i++) {
        k[i] = (av[i] != BLANK) && (av[i] != p) && (t0 + i < L);
        p = av[i];
        cnt += (int)k[i];
    }

    float loc = 0.f;
    loc += (t0 + 0 < L) ? M0.x : 0.f;
    loc += (t0 + 1 < L) ? M0.y : 0.f;
    loc += (t0 + 2 < L) ? M0.z : 0.f;
    loc += (t0 + 3 < L) ? M0.w : 0.f;
    loc += (t0 + 4 < L) ? M1.x : 0.f;
    loc += (t0 + 5 < L) ? M1.y : 0.f;
    loc += (t0 + 6 < L) ? M1.z : 0.f;
    loc += (t0 + 7 < L) ? M1.w : 0.f;

    int inc = cnt;
#pragma unroll
    for (int off = 1; off < 32; off <<= 1) {
        int v = __shfl_up_sync(0xffffffffu, inc, off);
        if (lane >= off) inc += v;
        loc += __shfl_down_sync(0xffffffffu, loc, off);
    }
    if (lane == 31) swc[wid] = inc;
    if (lane == 0)  sws[wid] = loc;
    __syncthreads();

    if (wid == 0) {
        int v = (lane < 8) ? swc[lane] : 0;
        int inc2 = v;
#pragma unroll
        for (int off = 1; off < 32; off <<= 1) {
            int u = __shfl_up_sync(0xffffffffu, inc2, off);
            if (lane >= off) inc2 += u;
        }
        if (lane < 8) swc[lane] = inc2 - v;          // exclusive warp offsets
        if (lane == 7)
            out[N_DIM + (size_t)T_DIM * N_DIM + n] = (float)inc2;  // out_lens

        float fs = (lane < 8) ? sws[lane] : 0.f;
#pragma unroll
        for (int off = 16; off; off >>= 1)
            fs += __shfl_down_sync(0xffffffffu, fs, off);
        if (lane == 0) out[n] = fs;                  // max_total
    }
    __syncthreads();

    int pos = swc[wid] + (inc - cnt);
    float* paths = out + N_DIM;
#pragma unroll
    for (int i = 0; i < 8; i++) {
        if (k[i]) { paths[pos * N_DIM + n] = (float)av[i]; pos++; }
    }
}

// ---------------------------------------------------------------------------
extern "C" void kernel_launch(void* const* d_in, const int* in_sizes, int n_in,
                              void* d_out, int out_size)
{
    const float* logits = (const float*)d_in[0];
    const void*  lens   = d_in[1];
    float* out = (float*)d_out;

    (void)in_sizes; (void)n_in; (void)out_size;

    // Kernel 1: T*N = 65536 warps -> 8192 blocks of 256 threads
    ctc_rowmax_kernel<<<(T_DIM * N_DIM) / 8, 256>>>(logits, out + N_DIM);

    // Kernel 2 with programmatic dependent launch: overlap its launch with K1.
    cudaLaunchConfig_t cfg = {};
    cfg.gridDim  = dim3(N_DIM, 1, 1);
    cfg.blockDim = dim3(256, 1, 1);
    cfg.dynamicSmemBytes = 0;
    cfg.stream = 0;
    cudaLaunchAttribute attrs[1];
    attrs[0].id = cudaLaunchAttributeProgrammaticStreamSerialization;
    attrs[0].val.programmaticStreamSerializationAllowed = 1;
    cfg.attrs = attrs;
    cfg.numAttrs = 1;
    cudaLaunchKernelEx(&cfg, ctc_scan_kernel, (const void*)lens, out);
}